// round 13
// baseline (speedup 1.0000x reference)
#include <cuda_runtime.h>

// waspGridSpatialIntegral: input [B=64, 2, W=512, W=512] fp32.
//   out[:,0,:,:] = cumsum(in[:,0,:,:], axis=-1)  (contiguous width)
//   out[:,1,:,:] = cumsum(in[:,1,:,:], axis=-2)  (height, stride W)
//
// Aggregate check: 268 MB / 42 us = 6.4 TB/s -> ~80% of spec; recoverable
// time is the column-only TAIL (columns are the critical path: R2->R3
// column-UNR change moved the kernel 5 us).
//
// R11 (retry): 2-way redundant-sum column split. 512 column blocks:
//   half 0 scans rows [0,256); half 1 first SUMS rows [0,256) (loads only;
//   overlaps half 0's concurrent reads of the same lines -> L2 dedups,
//   ~no extra DRAM), then scans rows [256,512) seeded with that sum.
//   Column warps 2x, serial depth 1/2, tail in-flight 4->8 MB. No sync.
// Rows identical to R3 (best measured). Outer loops rolled (R3 shape).

#define W      512
#define HW     256                  // half height
#define WW     (512 * 512)
#define B      64
#define NROWS  (B * W)              // 32768 channel-0 rows
#define NCOLB  (B * 4 * 2)          // 512 column blocks (img x 4 tiles x 2 halves)
#define UNR    32                   // column batch depth

__global__ __launch_bounds__(128) void wasp_integral_kernel(
    const float* __restrict__ in, float* __restrict__ out)
{
    const int bid = blockIdx.x;
    const int tid = threadIdx.x;

    if (bid < NCOLB) {
        // ------- channel 1: column scan (cumsum along y, stride W) -------
        const int b    = bid >> 3;
        const int tile = (bid >> 1) & 3;
        const int half = bid & 1;
        const int col  = tile * 128 + tid;
        const float* src = in  + (size_t)(b * 2 + 1) * WW + col;
        float*       dst = out + (size_t)(b * 2 + 1) * WW + col;

        float acc = 0.0f;

        if (half) {
            // redundant sum of rows [0, 256): loads only, no stores.
            for (int r = 0; r < HW; r += UNR) {
                float v[UNR];
                #pragma unroll
                for (int i = 0; i < UNR; ++i)
                    v[i] = src[(size_t)(r + i) * W];
                #pragma unroll
                for (int i = 0; i < UNR; ++i)
                    acc += v[i];
            }
        }

        // scan this half's rows [half*256, half*256+256)
        const int r0 = half * HW;
        for (int rr = 0; rr < HW; rr += UNR) {
            const int r = r0 + rr;
            float v[UNR];
            #pragma unroll
            for (int i = 0; i < UNR; ++i)               // 32 loads in flight
                v[i] = __ldcs(src + (size_t)(r + i) * W);
            #pragma unroll
            for (int i = 0; i < UNR; ++i) {
                acc += v[i];
                __stcs(dst + (size_t)(r + i) * W, acc);
            }
        }
    } else {
        // ------- channel 0: row scan (cumsum along x, contiguous) -------
        const int rowid = bid - NCOLB;
        const int b     = rowid >> 9;
        const int y     = rowid & 511;
        const size_t base = (size_t)(b * 2) * WW + (size_t)y * W;

        const float4* src = reinterpret_cast<const float4*>(in + base);
        float4*       dst = reinterpret_cast<float4*>(out + base);

        float4 v = __ldcs(src + tid);
        v.y += v.x; v.z += v.y; v.w += v.z;   // local inclusive scan of 4

        const int lane = tid & 31;
        const int wid  = tid >> 5;

        float t = v.w;                         // warp scan of thread totals
        #pragma unroll
        for (int d = 1; d < 32; d <<= 1) {
            float n = __shfl_up_sync(0xFFFFFFFFu, t, d);
            if (lane >= d) t += n;
        }

        __shared__ float wsum[4];
        if (lane == 31) wsum[wid] = t;
        __syncthreads();

        float off = t - v.w;                   // intra-warp exclusive prefix
        #pragma unroll
        for (int w = 0; w < 3; ++w)
            if (wid > w) off += wsum[w];

        v.x += off; v.y += off; v.z += off; v.w += off;
        __stcs(dst + tid, v);
    }
}

extern "C" void kernel_launch(void* const* d_in, const int* in_sizes, int n_in,
                              void* d_out, int out_size)
{
    const float* in  = (const float*)d_in[0];
    float*       out = (float*)d_out;
    wasp_integral_kernel<<<NCOLB + NROWS, 128>>>(in, out);
}

// round 14
// speedup vs baseline: 1.0075x; 1.0075x over previous
#include <cuda_runtime.h>

// waspGridSpatialIntegral: input [B=64, 2, W=512, W=512] fp32.
//   out[:,0,:,:] = cumsum(in[:,0,:,:], axis=-1)  (contiguous width)
//   out[:,1,:,:] = cumsum(in[:,1,:,:], axis=-2)  (height, stride W)
//
// R14: fixed 2-way redundant-sum column split. R13's version broke its own
// L2 dedup: half-0 scanned with __ldcs (evict-first), so half-1's seed
// re-reads of rows [0,256) missed L2 and added ~33 MB of DRAM traffic
// (exactly the observed 42->46 us regression). Now ALL column loads are
// ld.global.cg via asm volatile: L2-cached/default-evict (dedup works) and
// compiler-unreorderable (preserves the 32-load front batch that R9 showed
// plain loads destroy). Stores stay evict-first. Rows identical to R3.
//
//   blocks [0, 512)        : column half-scans, ch 1 (long pole first)
//   blocks [512, 512+32768): row scans, ch 0 (one 128-thr block per row)

#define W      512
#define HW     256                  // half height
#define WW     (512 * 512)
#define B      64
#define NROWS  (B * W)              // 32768 channel-0 rows
#define NCOLB  (B * 4 * 2)          // 512 column blocks (img x 4 tiles x 2 halves)
#define UNR    32                   // column batch depth

// L2-cached load, compiler-unreorderable (protects front-batching).
__device__ __forceinline__ float ldg_cg(const float* p) {
    float v;
    asm volatile("ld.global.cg.f32 %0, [%1];" : "=f"(v) : "l"(p));
    return v;
}

__global__ __launch_bounds__(128) void wasp_integral_kernel(
    const float* __restrict__ in, float* __restrict__ out)
{
    const int bid = blockIdx.x;
    const int tid = threadIdx.x;

    if (bid < NCOLB) {
        // ------- channel 1: column scan (cumsum along y, stride W) -------
        const int b    = bid >> 3;
        const int tile = (bid >> 1) & 3;
        const int half = bid & 1;           // adjacent bids = same tile's halves
        const int col  = tile * 128 + tid;
        const float* src = in  + (size_t)(b * 2 + 1) * WW + col;
        float*       dst = out + (size_t)(b * 2 + 1) * WW + col;

        float acc = 0.0f;

        if (half) {
            // seed: sum rows [0,256), loads only. Half-0 is concurrently
            // scanning the same lines with .cg loads -> these hit L2.
            for (int r = 0; r < HW; r += UNR) {
                float v[UNR];
                #pragma unroll
                for (int i = 0; i < UNR; ++i)
                    v[i] = ldg_cg(src + (size_t)(r + i) * W);
                #pragma unroll
                for (int i = 0; i < UNR; ++i)
                    acc += v[i];
            }
        }

        // scan this half's rows [half*256, half*256+256)
        const int r0 = half * HW;
        for (int rr = 0; rr < HW; rr += UNR) {
            const int r = r0 + rr;
            float v[UNR];
            #pragma unroll
            for (int i = 0; i < UNR; ++i)               // 32 loads in flight
                v[i] = ldg_cg(src + (size_t)(r + i) * W);
            #pragma unroll
            for (int i = 0; i < UNR; ++i) {
                acc += v[i];
                __stcs(dst + (size_t)(r + i) * W, acc);
            }
        }
    } else {
        // ------- channel 0: row scan (cumsum along x, contiguous) -------
        const int rowid = bid - NCOLB;
        const int b     = rowid >> 9;
        const int y     = rowid & 511;
        const size_t base = (size_t)(b * 2) * WW + (size_t)y * W;

        const float4* src = reinterpret_cast<const float4*>(in + base);
        float4*       dst = reinterpret_cast<float4*>(out + base);

        float4 v = __ldcs(src + tid);
        v.y += v.x; v.z += v.y; v.w += v.z;   // local inclusive scan of 4

        const int lane = tid & 31;
        const int wid  = tid >> 5;

        float t = v.w;                         // warp scan of thread totals
        #pragma unroll
        for (int d = 1; d < 32; d <<= 1) {
            float n = __shfl_up_sync(0xFFFFFFFFu, t, d);
            if (lane >= d) t += n;
        }

        __shared__ float wsum[4];
        if (lane == 31) wsum[wid] = t;
        __syncthreads();

        float off = t - v.w;                   // intra-warp exclusive prefix
        #pragma unroll
        for (int w = 0; w < 3; ++w)
            if (wid > w) off += wsum[w];

        v.x += off; v.y += off; v.z += off; v.w += off;
        __stcs(dst + tid, v);
    }
}

extern "C" void kernel_launch(void* const* d_in, const int* in_sizes, int n_in,
                              void* d_out, int out_size)
{
    const float* in  = (const float*)d_in[0];
    float*       out = (float*)d_out;
    wasp_integral_kernel<<<NCOLB + NROWS, 128>>>(in, out);
}

// round 15
// speedup vs baseline: 1.1375x; 1.1291x over previous
#include <cuda_runtime.h>

// waspGridSpatialIntegral: input [B=64, 2, W=512, W=512] fp32.
//   out[:,0,:,:] = cumsum(in[:,0,:,:], axis=-1)  (contiguous width)
//   out[:,1,:,:] = cumsum(in[:,1,:,:], axis=-2)  (height, stride W)
//
// FINAL: exact revert to the best measured configuration (R3: 42.0 us
// kernel, 46.5 us dur, DRAM 63.7%). Twelve measured variants confirmed
// each element of this shape:
//   - __ldcs column loads: keeps the 32-load batch register-resident
//     (plain loads let ptxas interleave load+add, -4 us regression in R9)
//   - UNR=32 single batch: beat UNR=8, tied 16/16 pipeline, beat 32/32
//     (which blew regs 40->72 and tanked occupancy)
//   - block-per-row rows: beat warp-per-row and 2-row variants
//   - 256 unsplit column blocks: beat both redundant-split variants
//     (+traffic / +regs exceeded the tail gain)
//   - columns at lowest blockIdx: long pole launches in wave 1
// Aggregate 268 MB / 42 us = 6.4 TB/s ~ 80% of spec: near the practical
// roof for this mixed contiguous+strided read/write pattern.

#define W      512
#define WW     (512 * 512)
#define B      64
#define NROWS  (B * W)              // 32768 channel-0 rows
#define CTILES 4                    // 512 cols / 128 threads
#define NCOLB  (B * CTILES)         // 256 channel-1 blocks
#define UNR    32                   // column batch depth (MLP per thread)

__global__ __launch_bounds__(128) void wasp_integral_kernel(
    const float* __restrict__ in, float* __restrict__ out)
{
    const int bid = blockIdx.x;
    const int tid = threadIdx.x;

    if (bid < NCOLB) {
        // ------- channel 1: column scan (cumsum along y, stride W) -------
        const int b    = bid >> 2;
        const int tile = bid & 3;
        const int col  = tile * 128 + tid;
        const float* src = in  + (size_t)(b * 2 + 1) * WW + col;
        float*       dst = out + (size_t)(b * 2 + 1) * WW + col;

        float acc = 0.0f;
        for (int r = 0; r < W; r += UNR) {
            float v[UNR];
            #pragma unroll
            for (int i = 0; i < UNR; ++i)               // 32 loads in flight
                v[i] = __ldcs(src + (size_t)(r + i) * W);
            #pragma unroll
            for (int i = 0; i < UNR; ++i) {
                acc += v[i];
                __stcs(dst + (size_t)(r + i) * W, acc);
            }
        }
    } else {
        // ------- channel 0: row scan (cumsum along x, contiguous) -------
        const int rowid = bid - NCOLB;
        const int b     = rowid >> 9;
        const int y     = rowid & 511;
        const size_t base = (size_t)(b * 2) * WW + (size_t)y * W;

        const float4* src = reinterpret_cast<const float4*>(in + base);
        float4*       dst = reinterpret_cast<float4*>(out + base);

        float4 v = __ldcs(src + tid);
        v.y += v.x; v.z += v.y; v.w += v.z;   // local inclusive scan of 4

        const int lane = tid & 31;
        const int wid  = tid >> 5;

        float t = v.w;                         // warp scan of thread totals
        #pragma unroll
        for (int d = 1; d < 32; d <<= 1) {
            float n = __shfl_up_sync(0xFFFFFFFFu, t, d);
            if (lane >= d) t += n;
        }

        __shared__ float wsum[4];
        if (lane == 31) wsum[wid] = t;
        __syncthreads();

        float off = t - v.w;                   // intra-warp exclusive prefix
        #pragma unroll
        for (int w = 0; w < 3; ++w)
            if (wid > w) off += wsum[w];

        v.x += off; v.y += off; v.z += off; v.w += off;
        __stcs(dst + tid, v);
    }
}

extern "C" void kernel_launch(void* const* d_in, const int* in_sizes, int n_in,
                              void* d_out, int out_size)
{
    const float* in  = (const float*)d_in[0];
    float*       out = (float*)d_out;
    wasp_integral_kernel<<<NCOLB + NROWS, 128>>>(in, out);
}